// round 4
// baseline (speedup 1.0000x reference)
#include <cuda_runtime.h>
#include <math.h>

// Problem constants
#define BB 2
#define TT 2048
#define CC 2048
#define HH 16
#define DD 128
#define MM (BB * TT)    // 4096 rows
#define N3 (3 * CC)     // 6144

// Scratch (no cudaMalloc allowed): qkv [4096,6144], y [4096,2048]
__device__ float g_qkv[(size_t)MM * N3];
__device__ float g_y[(size_t)MM * CC];

// ---------------------------------------------------------------------------
// SGEMM with bias: C[M,N] = A[M,K] @ B[K,N] + bias[N]
// BM=BN=128, BK=16, 256 threads, 8x8 per-thread register tile (split 4+4).
// All dims divisible by tile sizes for this problem (M=4096, N in {6144,2048}, K=2048).
// ---------------------------------------------------------------------------
__global__ __launch_bounds__(256, 2)
void sgemm_bias_kernel(const float* __restrict__ A,
                       const float* __restrict__ Bm,
                       const float* __restrict__ bias,
                       float* __restrict__ Co,
                       int Ndim, int Kdim)
{
    __shared__ float As[16][132];   // [k][m], padded (132*4=528B, 16B aligned)
    __shared__ float Bs[16][128];   // [k][n]

    const int tid = threadIdx.x;
    const int ty = tid >> 4;        // 0..15
    const int tx = tid & 15;        // 0..15
    const int row0 = blockIdx.y * 128;
    const int col0 = blockIdx.x * 128;

    float acc[8][8];
#pragma unroll
    for (int i = 0; i < 8; i++)
#pragma unroll
        for (int j = 0; j < 8; j++) acc[i][j] = 0.0f;

    const float* Ab = A + (size_t)row0 * Kdim;
    const float* Bb = Bm + col0;

    for (int k0 = 0; k0 < Kdim; k0 += 16) {
        // Load A tile 128x16, vectorized along K, store transposed As[k][m]
#pragma unroll
        for (int it = 0; it < 2; it++) {
            int idx = tid + it * 256;          // 0..511
            int r  = idx >> 2;                 // 0..127 (m)
            int cv = idx & 3;                  // k-group
            float4 v = *(const float4*)(Ab + (size_t)r * Kdim + k0 + cv * 4);
            As[cv * 4 + 0][r] = v.x;
            As[cv * 4 + 1][r] = v.y;
            As[cv * 4 + 2][r] = v.z;
            As[cv * 4 + 3][r] = v.w;
        }
        // Load B tile 16x128 (natural layout)
#pragma unroll
        for (int it = 0; it < 2; it++) {
            int idx = tid + it * 256;
            int r  = idx >> 5;                 // 0..15 (k)
            int cv = idx & 31;                 // n-group
            *(float4*)(&Bs[r][cv * 4]) = *(const float4*)(Bb + (size_t)(k0 + r) * Ndim + cv * 4);
        }
        __syncthreads();

#pragma unroll
        for (int kk = 0; kk < 16; kk++) {
            float ra[8], rb[8];
            *(float4*)&ra[0] = *(const float4*)(&As[kk][ty * 4]);
            *(float4*)&ra[4] = *(const float4*)(&As[kk][64 + ty * 4]);
            *(float4*)&rb[0] = *(const float4*)(&Bs[kk][tx * 4]);
            *(float4*)&rb[4] = *(const float4*)(&Bs[kk][64 + tx * 4]);
#pragma unroll
            for (int i = 0; i < 8; i++)
#pragma unroll
                for (int j = 0; j < 8; j++)
                    acc[i][j] = fmaf(ra[i], rb[j], acc[i][j]);
        }
        __syncthreads();
    }

    // Epilogue: add bias, write out
    float bv[8];
    *(float4*)&bv[0] = *(const float4*)(bias + col0 + tx * 4);
    *(float4*)&bv[4] = *(const float4*)(bias + col0 + 64 + tx * 4);
#pragma unroll
    for (int i = 0; i < 8; i++) {
        int r = row0 + ((i < 4) ? (ty * 4 + i) : (64 + ty * 4 + (i - 4)));
        float4 o0 = make_float4(acc[i][0] + bv[0], acc[i][1] + bv[1],
                                acc[i][2] + bv[2], acc[i][3] + bv[3]);
        float4 o1 = make_float4(acc[i][4] + bv[4], acc[i][5] + bv[5],
                                acc[i][6] + bv[6], acc[i][7] + bv[7]);
        *(float4*)(Co + (size_t)r * Ndim + col0 + tx * 4)      = o0;
        *(float4*)(Co + (size_t)r * Ndim + col0 + 64 + tx * 4) = o1;
    }
}

// ---------------------------------------------------------------------------
// Causal flash attention over g_qkv -> g_y.
// Grid: (T/64, H, B). 256 threads = 16x16; each thread: 4x4 of S, 4x8 of O.
// Online softmax; only k-tiles with kt <= qt are visited (causal skip).
// ---------------------------------------------------------------------------
#define FBM 64
#define FBN 64
#define QLD 68                       // padded row stride for Qs/Kt (272B, 16B aligned)
#define PLD 65                       // Ps row stride (scalar access only)
#define FLASH_SMEM ((size_t)(DD * QLD * 2 + FBN * DD + FBN * PLD) * sizeof(float))

__global__ __launch_bounds__(256, 1)
void flash_kernel()
{
    extern __shared__ float sm[];
    float* Qs = sm;                   // [DD][QLD]  (d-major, transposed)
    float* Kt = Qs + DD * QLD;        // [DD][QLD]
    float* Vs = Kt + DD * QLD;        // [FBN][DD]  (natural)
    float* Ps = Vs + FBN * DD;        // [FBM][PLD]

    const int tid = threadIdx.x;
    const int ty = tid >> 4;          // 0..15 -> S rows ty*4..+3
    const int tx = tid & 15;          // 0..15 -> S cols tx*4..+3, O cols tx*4 / 64+tx*4
    const int qt = blockIdx.x;
    const int h  = blockIdx.y;
    const int b  = blockIdx.z;
    const float scale = 0.08838834764831845f;  // 1/sqrt(128)

    const size_t base = ((size_t)b * TT) * N3 + (size_t)h * DD;
    const float* Qg = g_qkv + base;            // row stride N3
    const float* Kg = g_qkv + base + CC;
    const float* Vg = g_qkv + base + 2 * CC;
    const int q0 = qt * FBM;

    // Load Q tile (64 x 128) transposed + pre-scaled
#pragma unroll
    for (int it = 0; it < 8; it++) {
        int idx = tid + it * 256;      // 0..2047
        int r  = idx >> 5;             // row 0..63
        int cv = idx & 31;             // d-group
        float4 v = *(const float4*)(Qg + (size_t)(q0 + r) * N3 + cv * 4);
        Qs[(cv * 4 + 0) * QLD + r] = v.x * scale;
        Qs[(cv * 4 + 1) * QLD + r] = v.y * scale;
        Qs[(cv * 4 + 2) * QLD + r] = v.z * scale;
        Qs[(cv * 4 + 3) * QLD + r] = v.w * scale;
    }

    float m_run[4], l_run[4], acc[4][8];
#pragma unroll
    for (int i = 0; i < 4; i++) {
        m_run[i] = -1e30f;
        l_run[i] = 0.0f;
#pragma unroll
        for (int j = 0; j < 8; j++) acc[i][j] = 0.0f;
    }

    for (int kt = 0; kt <= qt; kt++) {
        const int kk0 = kt * FBN;
        __syncthreads();  // prior PV readers of Kt/Vs done; Qs stores visible (1st iter)

        // Load K (transposed into Kt[d][kc]) and V (natural Vs[kc][d])
#pragma unroll
        for (int it = 0; it < 8; it++) {
            int idx = tid + it * 256;
            int r  = idx >> 5;
            int cv = idx & 31;
            float4 v = *(const float4*)(Kg + (size_t)(kk0 + r) * N3 + cv * 4);
            Kt[(cv * 4 + 0) * QLD + r] = v.x;
            Kt[(cv * 4 + 1) * QLD + r] = v.y;
            Kt[(cv * 4 + 2) * QLD + r] = v.z;
            Kt[(cv * 4 + 3) * QLD + r] = v.w;
            float4 w = *(const float4*)(Vg + (size_t)(kk0 + r) * N3 + cv * 4);
            *(float4*)(&Vs[r * DD + cv * 4]) = w;
        }
        __syncthreads();

        // S = (Q*scale) @ K^T : 4x4 per thread
        float s[4][4];
#pragma unroll
        for (int i = 0; i < 4; i++)
#pragma unroll
            for (int j = 0; j < 4; j++) s[i][j] = 0.0f;

#pragma unroll 4
        for (int d = 0; d < DD; d++) {
            float ra[4], rb[4];
            *(float4*)ra = *(const float4*)(&Qs[d * QLD + ty * 4]);
            *(float4*)rb = *(const float4*)(&Kt[d * QLD + tx * 4]);
#pragma unroll
            for (int i = 0; i < 4; i++)
#pragma unroll
                for (int j = 0; j < 4; j++)
                    s[i][j] = fmaf(ra[i], rb[j], s[i][j]);
        }

        // Causal mask on the diagonal tile
        if (kt == qt) {
#pragma unroll
            for (int i = 0; i < 4; i++)
#pragma unroll
                for (int j = 0; j < 4; j++)
                    if (kk0 + tx * 4 + j > q0 + ty * 4 + i) s[i][j] = -1e30f;
        }

        // Row max (per thread over 4 cols, then over the 16 lanes of the row group)
        float mt[4];
#pragma unroll
        for (int i = 0; i < 4; i++)
            mt[i] = fmaxf(fmaxf(s[i][0], s[i][1]), fmaxf(s[i][2], s[i][3]));
#pragma unroll
        for (int off = 8; off > 0; off >>= 1)
#pragma unroll
            for (int i = 0; i < 4; i++)
                mt[i] = fmaxf(mt[i], __shfl_xor_sync(0xffffffffu, mt[i], off));

        float alpha[4], rs[4];
#pragma unroll
        for (int i = 0; i < 4; i++) {
            float mn = fmaxf(m_run[i], mt[i]);
            alpha[i] = __expf(m_run[i] - mn);
            m_run[i] = mn;
            float r0 = 0.0f;
#pragma unroll
            for (int j = 0; j < 4; j++) {
                s[i][j] = __expf(s[i][j] - mn);
                r0 += s[i][j];
            }
            rs[i] = r0;
        }
#pragma unroll
        for (int off = 8; off > 0; off >>= 1)
#pragma unroll
            for (int i = 0; i < 4; i++)
                rs[i] += __shfl_xor_sync(0xffffffffu, rs[i], off);
#pragma unroll
        for (int i = 0; i < 4; i++) {
            l_run[i] = l_run[i] * alpha[i] + rs[i];
#pragma unroll
            for (int j = 0; j < 8; j++) acc[i][j] *= alpha[i];
        }

        // Stage P in smem for the PV GEMM
#pragma unroll
        for (int i = 0; i < 4; i++)
#pragma unroll
            for (int j = 0; j < 4; j++)
                Ps[(ty * 4 + i) * PLD + tx * 4 + j] = s[i][j];
        __syncthreads();

        // O += P @ V : 4x8 per thread
#pragma unroll 2
        for (int kk = 0; kk < FBN; kk++) {
            float rp[4], rv[8];
#pragma unroll
            for (int i = 0; i < 4; i++) rp[i] = Ps[(ty * 4 + i) * PLD + kk];
            *(float4*)&rv[0] = *(const float4*)(&Vs[kk * DD + tx * 4]);
            *(float4*)&rv[4] = *(const float4*)(&Vs[kk * DD + 64 + tx * 4]);
#pragma unroll
            for (int i = 0; i < 4; i++)
#pragma unroll
                for (int j = 0; j < 8; j++)
                    acc[i][j] = fmaf(rp[i], rv[j], acc[i][j]);
        }
    }

    // Normalize and write y in [B,T,C] layout (head-interleaved)
#pragma unroll
    for (int i = 0; i < 4; i++) {
        float inv = 1.0f / l_run[i];
        int r = q0 + ty * 4 + i;
        float* yp = g_y + ((size_t)b * TT + r) * CC + (size_t)h * DD;
        float4 o0 = make_float4(acc[i][0] * inv, acc[i][1] * inv,
                                acc[i][2] * inv, acc[i][3] * inv);
        float4 o1 = make_float4(acc[i][4] * inv, acc[i][5] * inv,
                                acc[i][6] * inv, acc[i][7] * inv);
        *(float4*)(yp + tx * 4)      = o0;
        *(float4*)(yp + 64 + tx * 4) = o1;
    }
}

// ---------------------------------------------------------------------------
// Launch: qkv = x@W_attn+b -> flash attention -> out = y@W_proj+b
// ---------------------------------------------------------------------------
extern "C" void kernel_launch(void* const* d_in, const int* in_sizes, int n_in,
                              void* d_out, int out_size)
{
    (void)in_sizes; (void)n_in; (void)out_size;
    const float* x      = (const float*)d_in[0];
    const float* W_attn = (const float*)d_in[1];
    const float* b_attn = (const float*)d_in[2];
    const float* W_proj = (const float*)d_in[3];
    const float* b_proj = (const float*)d_in[4];
    float* out = (float*)d_out;

    float* qkv = nullptr;
    float* y   = nullptr;
    cudaGetSymbolAddress((void**)&qkv, g_qkv);
    cudaGetSymbolAddress((void**)&y, g_y);

    cudaFuncSetAttribute(flash_kernel,
                         cudaFuncAttributeMaxDynamicSharedMemorySize,
                         (int)FLASH_SMEM);

    // 1) QKV projection: [4096,2048] @ [2048,6144] + b_attn
    sgemm_bias_kernel<<<dim3(N3 / 128, MM / 128), 256>>>(x, W_attn, b_attn, qkv, N3, CC);

    // 2) Causal multi-head attention
    flash_kernel<<<dim3(TT / FBM, HH, BB), 256, FLASH_SMEM>>>();

    // 3) Output projection: [4096,2048] @ [2048,2048] + b_proj
    sgemm_bias_kernel<<<dim3(CC / 128, MM / 128), 256>>>(y, W_proj, b_proj, out, CC, CC);
}

// round 7
// speedup vs baseline: 1.5300x; 1.5300x over previous
#include <cuda_runtime.h>
#include <cuda_bf16.h>
#include <cstdint>
#include <math.h>

// Problem constants
#define BB 2
#define TT 2048
#define CC 2048
#define HH 16
#define DD 128
#define MM (BB * TT)    // 4096 rows
#define N3 (3 * CC)     // 6144

// Scratch (no cudaMalloc allowed)
__device__ float g_qkv[(size_t)MM * N3];                        // fp32 qkv
__device__ float g_y[(size_t)MM * CC];                          // fp32 attention out
__device__ __align__(16) __nv_bfloat16 g_ah[(size_t)MM * CC];   // A hi (x or y)
__device__ __align__(16) __nv_bfloat16 g_al[(size_t)MM * CC];   // A lo
__device__ __align__(16) __nv_bfloat16 g_bh[(size_t)N3 * CC];   // W^T hi
__device__ __align__(16) __nv_bfloat16 g_bl[(size_t)N3 * CC];   // W^T lo

// ---------------------------------------------------------------------------
// Base-target PTX helpers (NO tcgen05/TMEM — ptxas targets compute_103)
// ---------------------------------------------------------------------------
__device__ __forceinline__ uint32_t smem_u32(const void* p) {
    uint32_t a;
    asm("{ .reg .u64 t; cvta.to.shared.u64 t, %1; cvt.u32.u64 %0, t; }" : "=r"(a) : "l"(p));
    return a;
}

#define CP_ASYNC16(dst, src) asm volatile("cp.async.cg.shared.global [%0], [%1], 16;" :: "r"(dst), "l"(src))
#define CP_COMMIT()          asm volatile("cp.async.commit_group;" ::: "memory")
#define CP_WAIT0()           asm volatile("cp.async.wait_group 0;" ::: "memory")

__device__ __forceinline__ void ldsm_x4(uint32_t* r, uint32_t addr) {
    asm volatile("ldmatrix.sync.aligned.m8n8.x4.shared.b16 {%0,%1,%2,%3}, [%4];"
                 : "=r"(r[0]), "=r"(r[1]), "=r"(r[2]), "=r"(r[3]) : "r"(addr));
}
__device__ __forceinline__ void ldsm_x2(uint32_t* r, uint32_t addr) {
    asm volatile("ldmatrix.sync.aligned.m8n8.x2.shared.b16 {%0,%1}, [%2];"
                 : "=r"(r[0]), "=r"(r[1]) : "r"(addr));
}
__device__ __forceinline__ void mma16816(float* d, const uint32_t* a, const uint32_t* b) {
    asm volatile(
        "mma.sync.aligned.m16n8k16.row.col.f32.bf16.bf16.f32 "
        "{%0,%1,%2,%3}, {%4,%5,%6,%7}, {%8,%9}, {%0,%1,%2,%3};"
        : "+f"(d[0]), "+f"(d[1]), "+f"(d[2]), "+f"(d[3])
        : "r"(a[0]), "r"(a[1]), "r"(a[2]), "r"(a[3]), "r"(b[0]), "r"(b[1]));
}

// SW128 swizzle on byte offsets (128B rows)
#define SWZ(o) ((uint32_t)(o) ^ (((uint32_t)(o) >> 3) & 0x70u))

// ---------------------------------------------------------------------------
// Split kernels: fp32 -> bf16 hi + bf16 lo
// ---------------------------------------------------------------------------
__global__ void split_rm_kernel(const float* __restrict__ in,
                                __nv_bfloat16* __restrict__ oh,
                                __nv_bfloat16* __restrict__ ol, size_t n4)
{
    size_t i = (size_t)blockIdx.x * blockDim.x + threadIdx.x;
    if (i >= n4) return;
    float4 v = ((const float4*)in)[i];
    float f[4] = {v.x, v.y, v.z, v.w};
    __nv_bfloat16 h[4], l[4];
#pragma unroll
    for (int j = 0; j < 4; j++) {
        h[j] = __float2bfloat16_rn(f[j]);
        l[j] = __float2bfloat16_rn(f[j] - __bfloat162float(h[j]));
    }
    __nv_bfloat162 h0; h0.x = h[0]; h0.y = h[1];
    __nv_bfloat162 h1; h1.x = h[2]; h1.y = h[3];
    __nv_bfloat162 l0; l0.x = l[0]; l0.y = l[1];
    __nv_bfloat162 l1; l1.x = l[2]; l1.y = l[3];
    ((__nv_bfloat162*)oh)[2 * i]     = h0;
    ((__nv_bfloat162*)oh)[2 * i + 1] = h1;
    ((__nv_bfloat162*)ol)[2 * i]     = l0;
    ((__nv_bfloat162*)ol)[2 * i + 1] = l1;
}

// W [Kd, Nd] fp32 -> out [Nd, Kd] bf16 hi/lo (transpose via smem tile)
__global__ void split_tr_kernel(const float* __restrict__ in,
                                __nv_bfloat16* __restrict__ oh,
                                __nv_bfloat16* __restrict__ ol, int Kd, int Nd)
{
    __shared__ float t[32][33];
    int n0 = blockIdx.x * 32, k0 = blockIdx.y * 32;
    int tx = threadIdx.x & 31, ty = threadIdx.x >> 5;   // 256 thr: ty 0..7
#pragma unroll
    for (int r = 0; r < 32; r += 8)
        t[ty + r][tx] = in[(size_t)(k0 + ty + r) * Nd + n0 + tx];
    __syncthreads();
#pragma unroll
    for (int r = 0; r < 32; r += 8) {
        int n = ty + r;
        float v = t[tx][n];
        __nv_bfloat16 h = __float2bfloat16_rn(v);
        __nv_bfloat16 l = __float2bfloat16_rn(v - __bfloat162float(h));
        oh[(size_t)(n0 + n) * Kd + k0 + tx] = h;
        ol[(size_t)(n0 + n) * Kd + k0 + tx] = l;
    }
}

// ---------------------------------------------------------------------------
// bf16-split GEMM via ldmatrix + mma.sync (m16n8k16):
//   C[M,N] = A@B + bias;  A[M,K] row-major hi/lo, Bt[N,K] K-major hi/lo.
// BM=BN=128, BK=32, 256 threads = 8 warps (2 x 4), warp tile 64x32.
// smem rows pack [hi 64B | lo 64B] -> 128B rows, SW128 swizzle, double buffer.
// 3 MMA passes per tile pair: Ah*Bh + Ah*Bl + Al*Bh.
// ---------------------------------------------------------------------------
#define GBK 32
#define ATILE 16384                    // 128 rows * 128B
#define STAGE (2 * ATILE)              // A + B
#define G_SMEM (2 * STAGE)             // 65536

__global__ __launch_bounds__(256, 1)
void gemm_mma_kernel(const __nv_bfloat16* __restrict__ Ah,
                     const __nv_bfloat16* __restrict__ Al,
                     const __nv_bfloat16* __restrict__ Bh,
                     const __nv_bfloat16* __restrict__ Bl,
                     const float* __restrict__ bias,
                     float* __restrict__ Co, int Ndim, int Kdim)
{
    extern __shared__ char smem[];
    const uint32_t sb = smem_u32(smem);
    const int tid  = threadIdx.x;
    const int wid  = tid >> 5;
    const int lane = tid & 31;
    const int wm   = wid & 1;          // 0..1 -> M offset wm*64
    const int wn   = wid >> 1;         // 0..3 -> N offset wn*32
    const int row0 = blockIdx.y * 128;
    const int col0 = blockIdx.x * 128;

    const __nv_bfloat16* Ahp = Ah + (size_t)row0 * Kdim;
    const __nv_bfloat16* Alp = Al + (size_t)row0 * Kdim;
    const __nv_bfloat16* Bhp = Bh + (size_t)col0 * Kdim;
    const __nv_bfloat16* Blp = Bl + (size_t)col0 * Kdim;

    float acc[4][4][4];
#pragma unroll
    for (int i = 0; i < 4; i++)
#pragma unroll
        for (int j = 0; j < 4; j++)
#pragma unroll
            for (int k = 0; k < 4; k++) acc[i][j][k] = 0.0f;

    const int NCH = Kdim >> 5;

    // Tile loader: stage s, K offset k0. Row r: [hi k0..k0+31 | lo k0..k0+31]
    auto load_stage = [&](int s, int k0) {
        uint32_t as = sb + s * STAGE;
        uint32_t bs = as + ATILE;
#pragma unroll
        for (int it = 0; it < 4; it++) {
            int i = tid + it * 256;            // 0..1023
            int r = i >> 3, c = i & 7;
            uint32_t d = SWZ(r * 128 + c * 16);
            const __nv_bfloat16* sa = (c < 4)
                ? (Ahp + (size_t)r * Kdim + k0 + c * 8)
                : (Alp + (size_t)r * Kdim + k0 + (c - 4) * 8);
            CP_ASYNC16(as + d, sa);
            const __nv_bfloat16* sbp = (c < 4)
                ? (Bhp + (size_t)r * Kdim + k0 + c * 8)
                : (Blp + (size_t)r * Kdim + k0 + (c - 4) * 8);
            CP_ASYNC16(bs + d, sbp);
        }
    };

    load_stage(0, 0);
    CP_COMMIT();
    CP_WAIT0();
    __syncthreads();

    for (int ch = 0; ch < NCH; ch++) {
        if (ch + 1 < NCH) load_stage((ch + 1) & 1, (ch + 1) * GBK);
        CP_COMMIT();

        const uint32_t as = sb + (ch & 1) * STAGE;
        const uint32_t bs = as + ATILE;

#pragma unroll
        for (int ks = 0; ks < 2; ks++) {
            // A fragments (hi + lo): 4 m-tiles
            uint32_t ah[4][4], al[4][4];
            {
                const int arow = wm * 64 + (lane & 15);
                const uint32_t kb = (uint32_t)(ks * 32 + ((lane >> 4) << 4));
#pragma unroll
                for (int mt = 0; mt < 4; mt++) {
                    uint32_t base = (uint32_t)((arow + mt * 16) * 128);
                    ldsm_x4(ah[mt], as + SWZ(base + kb));
                    ldsm_x4(al[mt], as + SWZ(base + kb + 64));
                }
            }
            // B fragments (hi + lo): 4 n-tiles
            uint32_t bh[4][2], bl[4][2];
            {
                const int nrow = wn * 32 + (lane & 7);
                const uint32_t kb = (uint32_t)(ks * 32 + (((lane >> 3) & 1) << 4));
#pragma unroll
                for (int nt = 0; nt < 4; nt++) {
                    uint32_t base = (uint32_t)((nrow + nt * 8) * 128);
                    ldsm_x2(bh[nt], bs + SWZ(base + kb));
                    ldsm_x2(bl[nt], bs + SWZ(base + kb + 64));
                }
            }
            // 48 MMAs: hh, hl, lh
#pragma unroll
            for (int mt = 0; mt < 4; mt++)
#pragma unroll
                for (int nt = 0; nt < 4; nt++) {
                    mma16816(acc[mt][nt], ah[mt], bh[nt]);
                    mma16816(acc[mt][nt], ah[mt], bl[nt]);
                    mma16816(acc[mt][nt], al[mt], bh[nt]);
                }
        }

        CP_WAIT0();
        __syncthreads();
    }

    // Epilogue: fragment scatter + bias
    const int g = lane >> 2;
    const int cg = lane & 3;
#pragma unroll
    for (int mt = 0; mt < 4; mt++) {
#pragma unroll
        for (int nt = 0; nt < 4; nt++) {
            int row = row0 + wm * 64 + mt * 16 + g;
            int col = col0 + wn * 32 + nt * 8 + cg * 2;
            float b0 = __ldg(bias + col);
            float b1 = __ldg(bias + col + 1);
            float2 o0 = make_float2(acc[mt][nt][0] + b0, acc[mt][nt][1] + b1);
            float2 o1 = make_float2(acc[mt][nt][2] + b0, acc[mt][nt][3] + b1);
            *(float2*)(Co + (size_t)row * Ndim + col)       = o0;
            *(float2*)(Co + (size_t)(row + 8) * Ndim + col) = o1;
        }
    }
}

// ---------------------------------------------------------------------------
// Causal flash attention over g_qkv -> g_y (unchanged, known-passing).
// ---------------------------------------------------------------------------
#define FBM 64
#define FBN 64
#define QLD 68
#define PLD 65
#define FLASH_SMEM ((size_t)(DD * QLD * 2 + FBN * DD + FBN * PLD) * sizeof(float))

__global__ __launch_bounds__(256, 1)
void flash_kernel()
{
    extern __shared__ float sm[];
    float* Qs = sm;
    float* Kt = Qs + DD * QLD;
    float* Vs = Kt + DD * QLD;
    float* Ps = Vs + FBN * DD;

    const int tid = threadIdx.x;
    const int ty = tid >> 4;
    const int tx = tid & 15;
    const int qt = blockIdx.x;
    const int h  = blockIdx.y;
    const int b  = blockIdx.z;
    const float scale = 0.08838834764831845f;

    const size_t base = ((size_t)b * TT) * N3 + (size_t)h * DD;
    const float* Qg = g_qkv + base;
    const float* Kg = g_qkv + base + CC;
    const float* Vg = g_qkv + base + 2 * CC;
    const int q0 = qt * FBM;

#pragma unroll
    for (int it = 0; it < 8; it++) {
        int idx = tid + it * 256;
        int r  = idx >> 5;
        int cv = idx & 31;
        float4 v = *(const float4*)(Qg + (size_t)(q0 + r) * N3 + cv * 4);
        Qs[(cv * 4 + 0) * QLD + r] = v.x * scale;
        Qs[(cv * 4 + 1) * QLD + r] = v.y * scale;
        Qs[(cv * 4 + 2) * QLD + r] = v.z * scale;
        Qs[(cv * 4 + 3) * QLD + r] = v.w * scale;
    }

    float m_run[4], l_run[4], acc[4][8];
#pragma unroll
    for (int i = 0; i < 4; i++) {
        m_run[i] = -1e30f;
        l_run[i] = 0.0f;
#pragma unroll
        for (int j = 0; j < 8; j++) acc[i][j] = 0.0f;
    }

    for (int kt = 0; kt <= qt; kt++) {
        const int kk0 = kt * FBN;
        __syncthreads();

#pragma unroll
        for (int it = 0; it < 8; it++) {
            int idx = tid + it * 256;
            int r  = idx >> 5;
            int cv = idx & 31;
            float4 v = *(const float4*)(Kg + (size_t)(kk0 + r) * N3 + cv * 4);
            Kt[(cv * 4 + 0) * QLD + r] = v.x;
            Kt[(cv * 4 + 1) * QLD + r] = v.y;
            Kt[(cv * 4 + 2) * QLD + r] = v.z;
            Kt[(cv * 4 + 3) * QLD + r] = v.w;
            float4 w = *(const float4*)(Vg + (size_t)(kk0 + r) * N3 + cv * 4);
            *(float4*)(&Vs[r * DD + cv * 4]) = w;
        }
        __syncthreads();

        float s[4][4];
#pragma unroll
        for (int i = 0; i < 4; i++)
#pragma unroll
            for (int j = 0; j < 4; j++) s[i][j] = 0.0f;

#pragma unroll 4
        for (int d = 0; d < DD; d++) {
            float ra[4], rb[4];
            *(float4*)ra = *(const float4*)(&Qs[d * QLD + ty * 4]);
            *(float4*)rb = *(const float4*)(&Kt[d * QLD + tx * 4]);
#pragma unroll
            for (int i = 0; i < 4; i++)
#pragma unroll
                for (int j = 0; j < 4; j++)
                    s[i][j] = fmaf(ra[i], rb[j], s[i][j]);
        }

        if (kt == qt) {
#pragma unroll
            for (int i = 0; i < 4; i++)
#pragma unroll
                for (int j = 0; j < 4; j++)
                    if (kk0 + tx * 4 + j > q0 + ty * 4 + i) s[i][j] = -1e30f;
        }

        float mt[4];
#pragma unroll
        for (int i = 0; i < 4; i++)
            mt[i] = fmaxf(fmaxf(s[i][0], s[i][1]), fmaxf(s[i][2], s[i][3]));
#pragma unroll
        for (int off = 8; off > 0; off >>= 1)
#pragma unroll
            for (int i = 0; i < 4; i++)
                mt[i] = fmaxf(mt[i], __shfl_xor_sync(0xffffffffu, mt[i], off));

        float alpha[4], rs[4];
#pragma unroll
        for (int i = 0; i < 4; i++) {
            float mn = fmaxf(m_run[i], mt[i]);
            alpha[i] = __expf(m_run[i] - mn);
            m_run[i] = mn;
            float r0 = 0.0f;
#pragma unroll
            for (int j = 0; j < 4; j++) {
                s[i][j] = __expf(s[i][j] - mn);
                r0 += s[i][j];
            }
            rs[i] = r0;
        }
#pragma unroll
        for (int off = 8; off > 0; off >>= 1)
#pragma unroll
            for (int i = 0; i < 4; i++)
                rs[i] += __shfl_xor_sync(0xffffffffu, rs[i], off);
#pragma unroll
        for (int i = 0; i < 4; i++) {
            l_run[i] = l_run[i] * alpha[i] + rs[i];
#pragma unroll
            for (int j = 0; j < 8; j++) acc[i][j] *= alpha[i];
        }

#pragma unroll
        for (int i = 0; i < 4; i++)
#pragma unroll
            for (int j = 0; j < 4; j++)
                Ps[(ty * 4 + i) * PLD + tx * 4 + j] = s[i][j];
        __syncthreads();

#pragma unroll 2
        for (int kk = 0; kk < FBN; kk++) {
            float rp[4], rv[8];
#pragma unroll
            for (int i = 0; i < 4; i++) rp[i] = Ps[(ty * 4 + i) * PLD + kk];
            *(float4*)&rv[0] = *(const float4*)(&Vs[kk * DD + tx * 4]);
            *(float4*)&rv[4] = *(const float4*)(&Vs[kk * DD + 64 + tx * 4]);
#pragma unroll
            for (int i = 0; i < 4; i++)
#pragma unroll
                for (int j = 0; j < 8; j++)
                    acc[i][j] = fmaf(rp[i], rv[j], acc[i][j]);
        }
    }

#pragma unroll
    for (int i = 0; i < 4; i++) {
        float inv = 1.0f / l_run[i];
        int r = q0 + ty * 4 + i;
        float* yp = g_y + ((size_t)b * TT + r) * CC + (size_t)h * DD;
        float4 o0 = make_float4(acc[i][0] * inv, acc[i][1] * inv,
                                acc[i][2] * inv, acc[i][3] * inv);
        float4 o1 = make_float4(acc[i][4] * inv, acc[i][5] * inv,
                                acc[i][6] * inv, acc[i][7] * inv);
        *(float4*)(yp + tx * 4)      = o0;
        *(float4*)(yp + 64 + tx * 4) = o1;
    }
}

// ---------------------------------------------------------------------------
// Launch sequence
// ---------------------------------------------------------------------------
extern "C" void kernel_launch(void* const* d_in, const int* in_sizes, int n_in,
                              void* d_out, int out_size)
{
    (void)in_sizes; (void)n_in; (void)out_size;
    const float* x      = (const float*)d_in[0];
    const float* W_attn = (const float*)d_in[1];
    const float* b_attn = (const float*)d_in[2];
    const float* W_proj = (const float*)d_in[3];
    const float* b_proj = (const float*)d_in[4];
    float* out = (float*)d_out;

    float* qkv = nullptr; float* y = nullptr;
    __nv_bfloat16 *ah = nullptr, *al = nullptr, *bh = nullptr, *bl = nullptr;
    cudaGetSymbolAddress((void**)&qkv, g_qkv);
    cudaGetSymbolAddress((void**)&y,   g_y);
    cudaGetSymbolAddress((void**)&ah,  g_ah);
    cudaGetSymbolAddress((void**)&al,  g_al);
    cudaGetSymbolAddress((void**)&bh,  g_bh);
    cudaGetSymbolAddress((void**)&bl,  g_bl);

    cudaFuncSetAttribute(flash_kernel, cudaFuncAttributeMaxDynamicSharedMemorySize,
                         (int)FLASH_SMEM);
    cudaFuncSetAttribute(gemm_mma_kernel, cudaFuncAttributeMaxDynamicSharedMemorySize,
                         (int)G_SMEM);

    const size_t n4 = (size_t)MM * CC / 4;

    // 1) QKV projection: bf16-split mma.sync GEMM
    split_rm_kernel<<<(unsigned)((n4 + 255) / 256), 256>>>(x, ah, al, n4);
    split_tr_kernel<<<dim3(N3 / 32, CC / 32), 256>>>(W_attn, bh, bl, CC, N3);
    gemm_mma_kernel<<<dim3(N3 / 128, MM / 128), 256, G_SMEM>>>(ah, al, bh, bl,
                                                               b_attn, qkv, N3, CC);
    // 2) Causal multi-head attention (fp32 SIMT)
    flash_kernel<<<dim3(TT / FBM, HH, BB), 256, FLASH_SMEM>>>();

    // 3) Output projection: bf16-split mma.sync GEMM
    split_rm_kernel<<<(unsigned)((n4 + 255) / 256), 256>>>(y, ah, al, n4);
    split_tr_kernel<<<dim3(CC / 32, CC / 32), 256>>>(W_proj, bh, bl, CC, CC);
    gemm_mma_kernel<<<dim3(CC / 128, MM / 128), 256, G_SMEM>>>(ah, al, bh, bl,
                                                               b_proj, out, CC, CC);
}

// round 9
// speedup vs baseline: 2.5376x; 1.6586x over previous
#include <cuda_runtime.h>
#include <cuda_bf16.h>
#include <cstdint>
#include <math.h>

// Problem constants
#define BB 2
#define TT 2048
#define CC 2048
#define HH 16
#define DD 128
#define MM (BB * TT)    // 4096 rows
#define N3 (3 * CC)     // 6144

// Scratch (no cudaMalloc allowed)
__device__ float g_qkv[(size_t)MM * N3];                        // fp32 qkv
__device__ float g_y[(size_t)MM * CC];                          // fp32 attention out
__device__ __align__(16) __nv_bfloat16 g_ah[(size_t)MM * CC];   // A hi (x or y)
__device__ __align__(16) __nv_bfloat16 g_al[(size_t)MM * CC];   // A lo
__device__ __align__(16) __nv_bfloat16 g_bh[(size_t)N3 * CC];   // W^T hi
__device__ __align__(16) __nv_bfloat16 g_bl[(size_t)N3 * CC];   // W^T lo

// ---------------------------------------------------------------------------
// Base-target PTX helpers (NO tcgen05/TMEM — ptxas targets compute_103)
// ---------------------------------------------------------------------------
__device__ __forceinline__ uint32_t smem_u32(const void* p) {
    uint32_t a;
    asm("{ .reg .u64 t; cvta.to.shared.u64 t, %1; cvt.u32.u64 %0, t; }" : "=r"(a) : "l"(p));
    return a;
}

#define CP_ASYNC16(dst, src) asm volatile("cp.async.cg.shared.global [%0], [%1], 16;" :: "r"(dst), "l"(src))
#define CP_COMMIT()          asm volatile("cp.async.commit_group;" ::: "memory")
#define CP_WAIT0()           asm volatile("cp.async.wait_group 0;" ::: "memory")

__device__ __forceinline__ void ldsm_x4(uint32_t* r, uint32_t addr) {
    asm volatile("ldmatrix.sync.aligned.m8n8.x4.shared.b16 {%0,%1,%2,%3}, [%4];"
                 : "=r"(r[0]), "=r"(r[1]), "=r"(r[2]), "=r"(r[3]) : "r"(addr));
}
__device__ __forceinline__ void ldsm_x2(uint32_t* r, uint32_t addr) {
    asm volatile("ldmatrix.sync.aligned.m8n8.x2.shared.b16 {%0,%1}, [%2];"
                 : "=r"(r[0]), "=r"(r[1]) : "r"(addr));
}
__device__ __forceinline__ void ldsm_x2_t(uint32_t* r, uint32_t addr) {
    asm volatile("ldmatrix.sync.aligned.m8n8.x2.trans.shared.b16 {%0,%1}, [%2];"
                 : "=r"(r[0]), "=r"(r[1]) : "r"(addr));
}
__device__ __forceinline__ void mma16816(float* d, const uint32_t* a, const uint32_t* b) {
    asm volatile(
        "mma.sync.aligned.m16n8k16.row.col.f32.bf16.bf16.f32 "
        "{%0,%1,%2,%3}, {%4,%5,%6,%7}, {%8,%9}, {%0,%1,%2,%3};"
        : "+f"(d[0]), "+f"(d[1]), "+f"(d[2]), "+f"(d[3])
        : "r"(a[0]), "r"(a[1]), "r"(a[2]), "r"(a[3]), "r"(b[0]), "r"(b[1]));
}

// SW128 swizzle on byte offsets (128B rows)
#define SWZ(o) ((uint32_t)(o) ^ (((uint32_t)(o) >> 3) & 0x70u))

__device__ __forceinline__ uint32_t pack_bf2(float a, float b) {
    __nv_bfloat162 t = __floats2bfloat162_rn(a, b);
    return *reinterpret_cast<uint32_t*>(&t);
}

// Split a float4 into packed bf16 hi (uint2) and lo (uint2)
__device__ __forceinline__ void split4(float4 v, uint2& hi, uint2& lo) {
    __nv_bfloat16 h0 = __float2bfloat16_rn(v.x);
    __nv_bfloat16 h1 = __float2bfloat16_rn(v.y);
    __nv_bfloat16 h2 = __float2bfloat16_rn(v.z);
    __nv_bfloat16 h3 = __float2bfloat16_rn(v.w);
    __nv_bfloat162 a; a.x = h0; a.y = h1;
    __nv_bfloat162 b; b.x = h2; b.y = h3;
    hi.x = *reinterpret_cast<uint32_t*>(&a);
    hi.y = *reinterpret_cast<uint32_t*>(&b);
    lo.x = pack_bf2(v.x - __bfloat162float(h0), v.y - __bfloat162float(h1));
    lo.y = pack_bf2(v.z - __bfloat162float(h2), v.w - __bfloat162float(h3));
}

// ---------------------------------------------------------------------------
// Split kernels: fp32 -> bf16 hi + bf16 lo
// ---------------------------------------------------------------------------
__global__ void split_rm_kernel(const float* __restrict__ in,
                                __nv_bfloat16* __restrict__ oh,
                                __nv_bfloat16* __restrict__ ol, size_t n4)
{
    size_t i = (size_t)blockIdx.x * blockDim.x + threadIdx.x;
    if (i >= n4) return;
    float4 v = ((const float4*)in)[i];
    uint2 hi, lo;
    split4(v, hi, lo);
    ((uint2*)oh)[i] = hi;
    ((uint2*)ol)[i] = lo;
}

// W [Kd, Nd] fp32 -> out [Nd, Kd] bf16 hi/lo (transpose via smem tile)
__global__ void split_tr_kernel(const float* __restrict__ in,
                                __nv_bfloat16* __restrict__ oh,
                                __nv_bfloat16* __restrict__ ol, int Kd, int Nd)
{
    __shared__ float t[32][33];
    int n0 = blockIdx.x * 32, k0 = blockIdx.y * 32;
    int tx = threadIdx.x & 31, ty = threadIdx.x >> 5;   // 256 thr: ty 0..7
#pragma unroll
    for (int r = 0; r < 32; r += 8)
        t[ty + r][tx] = in[(size_t)(k0 + ty + r) * Nd + n0 + tx];
    __syncthreads();
#pragma unroll
    for (int r = 0; r < 32; r += 8) {
        int n = ty + r;
        float v = t[tx][n];
        __nv_bfloat16 h = __float2bfloat16_rn(v);
        __nv_bfloat16 l = __float2bfloat16_rn(v - __bfloat162float(h));
        oh[(size_t)(n0 + n) * Kd + k0 + tx] = h;
        ol[(size_t)(n0 + n) * Kd + k0 + tx] = l;
    }
}

// ---------------------------------------------------------------------------
// bf16-split GEMM via ldmatrix + mma.sync (m16n8k16)  [unchanged, passing]
// ---------------------------------------------------------------------------
#define GBK 32
#define ATILE 16384
#define STAGE (2 * ATILE)
#define G_SMEM (2 * STAGE)

__global__ __launch_bounds__(256, 1)
void gemm_mma_kernel(const __nv_bfloat16* __restrict__ Ah,
                     const __nv_bfloat16* __restrict__ Al,
                     const __nv_bfloat16* __restrict__ Bh,
                     const __nv_bfloat16* __restrict__ Bl,
                     const float* __restrict__ bias,
                     float* __restrict__ Co, int Ndim, int Kdim)
{
    extern __shared__ char smem[];
    const uint32_t sb = smem_u32(smem);
    const int tid  = threadIdx.x;
    const int wid  = tid >> 5;
    const int lane = tid & 31;
    const int wm   = wid & 1;
    const int wn   = wid >> 1;
    const int row0 = blockIdx.y * 128;
    const int col0 = blockIdx.x * 128;

    const __nv_bfloat16* Ahp = Ah + (size_t)row0 * Kdim;
    const __nv_bfloat16* Alp = Al + (size_t)row0 * Kdim;
    const __nv_bfloat16* Bhp = Bh + (size_t)col0 * Kdim;
    const __nv_bfloat16* Blp = Bl + (size_t)col0 * Kdim;

    float acc[4][4][4];
#pragma unroll
    for (int i = 0; i < 4; i++)
#pragma unroll
        for (int j = 0; j < 4; j++)
#pragma unroll
            for (int k = 0; k < 4; k++) acc[i][j][k] = 0.0f;

    const int NCH = Kdim >> 5;

    auto load_stage = [&](int s, int k0) {
        uint32_t as = sb + s * STAGE;
        uint32_t bs = as + ATILE;
#pragma unroll
        for (int it = 0; it < 4; it++) {
            int i = tid + it * 256;
            int r = i >> 3, c = i & 7;
            uint32_t d = SWZ(r * 128 + c * 16);
            const __nv_bfloat16* sa = (c < 4)
                ? (Ahp + (size_t)r * Kdim + k0 + c * 8)
                : (Alp + (size_t)r * Kdim + k0 + (c - 4) * 8);
            CP_ASYNC16(as + d, sa);
            const __nv_bfloat16* sbp = (c < 4)
                ? (Bhp + (size_t)r * Kdim + k0 + c * 8)
                : (Blp + (size_t)r * Kdim + k0 + (c - 4) * 8);
            CP_ASYNC16(bs + d, sbp);
        }
    };

    load_stage(0, 0);
    CP_COMMIT();
    CP_WAIT0();
    __syncthreads();

    for (int ch = 0; ch < NCH; ch++) {
        if (ch + 1 < NCH) load_stage((ch + 1) & 1, (ch + 1) * GBK);
        CP_COMMIT();

        const uint32_t as = sb + (ch & 1) * STAGE;
        const uint32_t bs = as + ATILE;

#pragma unroll
        for (int ks = 0; ks < 2; ks++) {
            uint32_t ah[4][4], al[4][4];
            {
                const int arow = wm * 64 + (lane & 15);
                const uint32_t kb = (uint32_t)(ks * 32 + ((lane >> 4) << 4));
#pragma unroll
                for (int mt = 0; mt < 4; mt++) {
                    uint32_t base = (uint32_t)((arow + mt * 16) * 128);
                    ldsm_x4(ah[mt], as + SWZ(base + kb));
                    ldsm_x4(al[mt], as + SWZ(base + kb + 64));
                }
            }
            uint32_t bh[4][2], bl[4][2];
            {
                const int nrow = wn * 32 + (lane & 7);
                const uint32_t kb = (uint32_t)(ks * 32 + (((lane >> 3) & 1) << 4));
#pragma unroll
                for (int nt = 0; nt < 4; nt++) {
                    uint32_t base = (uint32_t)((nrow + nt * 8) * 128);
                    ldsm_x2(bh[nt], bs + SWZ(base + kb));
                    ldsm_x2(bl[nt], bs + SWZ(base + kb + 64));
                }
            }
#pragma unroll
            for (int mt = 0; mt < 4; mt++)
#pragma unroll
                for (int nt = 0; nt < 4; nt++) {
                    mma16816(acc[mt][nt], ah[mt], bh[nt]);
                    mma16816(acc[mt][nt], ah[mt], bl[nt]);
                    mma16816(acc[mt][nt], al[mt], bh[nt]);
                }
        }

        CP_WAIT0();
        __syncthreads();
    }

    const int g = lane >> 2;
    const int cg = lane & 3;
#pragma unroll
    for (int mt = 0; mt < 4; mt++) {
#pragma unroll
        for (int nt = 0; nt < 4; nt++) {
            int row = row0 + wm * 64 + mt * 16 + g;
            int col = col0 + wn * 32 + nt * 8 + cg * 2;
            float b0 = __ldg(bias + col);
            float b1 = __ldg(bias + col + 1);
            float2 o0 = make_float2(acc[mt][nt][0] + b0, acc[mt][nt][1] + b1);
            float2 o1 = make_float2(acc[mt][nt][2] + b0, acc[mt][nt][3] + b1);
            *(float2*)(Co + (size_t)row * Ndim + col)       = o0;
            *(float2*)(Co + (size_t)(row + 8) * Ndim + col) = o1;
        }
    }
}

// ---------------------------------------------------------------------------
// Tensor-core causal flash attention: g_qkv -> g_y
// BM=128 q rows/block, BN=64 keys/tile, 256 threads = 8 warps x 16-row strips.
// Q/K/V in smem as bf16 hi/lo, SW128 panels of 64 d (128B rows).
// S via ldsm_x4/ldsm_x2 + mma (3-pass split); softmax in C-fragments
// (quad shfl reductions); P packed in-register to A-frags (hi + lo);
// PV via ldmatrix.x2.trans on natural V layout.
// ---------------------------------------------------------------------------
#define F_QH 0          // 2 panels * 16384
#define F_QL 32768
#define F_KH 65536      // 2 panels * 8192
#define F_KL 81920
#define F_VH 98304      // 2 panels * 8192
#define F_VL 114688
#define FLASH_SMEM 131072

__global__ __launch_bounds__(256, 1)
void flash_kernel()
{
    extern __shared__ char fsm[];
    const uint32_t sq = smem_u32(fsm);
    const int tid  = threadIdx.x;
    const int wid  = tid >> 5;
    const int lane = tid & 31;
    const int qt = blockIdx.x;
    const int h  = blockIdx.y;
    const int b  = blockIdx.z;
    const float scale = 0.08838834764831845f;  // 1/sqrt(128)

    const size_t base = ((size_t)b * TT) * N3 + (size_t)h * DD;
    const float* Qg = g_qkv + base;            // row stride N3
    const float* Kg = g_qkv + base + CC;
    const float* Vg = g_qkv + base + 2 * CC;
    const int q0 = qt * 128;

    // ---- Load Q tile (128 x 128) once: scale, split, swizzled panels ----
#pragma unroll
    for (int it = 0; it < 16; it++) {
        int idx = tid + it * 256;              // 0..4095
        int r = idx >> 5, c = idx & 31;        // r=q row, c=chunk of 4 d
        float4 v = *(const float4*)(Qg + (size_t)(q0 + r) * N3 + c * 4);
        v.x *= scale; v.y *= scale; v.z *= scale; v.w *= scale;
        uint2 hi, lo;
        split4(v, hi, lo);
        int p = c >> 4;
        uint32_t off = SWZ((uint32_t)(r * 128 + (c & 15) * 8));
        *(uint2*)(fsm + F_QH + p * 16384 + off) = hi;
        *(uint2*)(fsm + F_QL + p * 16384 + off) = lo;
    }

    // ---- State ----
    float o[16][4];
#pragma unroll
    for (int i = 0; i < 16; i++)
#pragma unroll
        for (int j = 0; j < 4; j++) o[i][j] = 0.0f;
    float m0 = -1e30f, m1 = -1e30f, l0 = 0.0f, l1 = 0.0f;

    const int nkt = 2 * qt + 2;

    for (int kt = 0; kt < nkt; kt++) {
        const int kk0 = kt * 64;
        __syncthreads();
        // ---- Load K, V tiles (64 x 128) ----
#pragma unroll
        for (int it = 0; it < 8; it++) {
            int idx = tid + it * 256;          // 0..2047
            int r = idx >> 5, c = idx & 31;
            int p = c >> 4;
            uint32_t off = SWZ((uint32_t)(r * 128 + (c & 15) * 8));
            float4 kv = *(const float4*)(Kg + (size_t)(kk0 + r) * N3 + c * 4);
            uint2 hi, lo;
            split4(kv, hi, lo);
            *(uint2*)(fsm + F_KH + p * 8192 + off) = hi;
            *(uint2*)(fsm + F_KL + p * 8192 + off) = lo;
            float4 vv = *(const float4*)(Vg + (size_t)(kk0 + r) * N3 + c * 4);
            split4(vv, hi, lo);
            *(uint2*)(fsm + F_VH + p * 8192 + off) = hi;
            *(uint2*)(fsm + F_VL + p * 8192 + off) = lo;
        }
        __syncthreads();

        // ---- S = Q @ K^T (3-pass split) ----
        float s[8][4];
#pragma unroll
        for (int nt = 0; nt < 8; nt++)
#pragma unroll
            for (int j = 0; j < 4; j++) s[nt][j] = 0.0f;

#pragma unroll
        for (int ks = 0; ks < 8; ks++) {
            const int p = ks >> 2;
            uint32_t ah[4], al[4];
            {
                uint32_t kb = (uint32_t)((ks & 3) * 32 + ((lane >> 4) << 4));
                uint32_t bofs = (uint32_t)((wid * 16 + (lane & 15)) * 128) + kb;
                ldsm_x4(ah, sq + F_QH + p * 16384 + SWZ(bofs));
                ldsm_x4(al, sq + F_QL + p * 16384 + SWZ(bofs));
            }
            uint32_t kb2 = (uint32_t)((ks & 3) * 32 + (((lane >> 3) & 1) << 4));
#pragma unroll
            for (int nt = 0; nt < 8; nt++) {
                uint32_t bofs = (uint32_t)((nt * 8 + (lane & 7)) * 128) + kb2;
                uint32_t bh2[2], bl2[2];
                ldsm_x2(bh2, sq + F_KH + p * 8192 + SWZ(bofs));
                ldsm_x2(bl2, sq + F_KL + p * 8192 + SWZ(bofs));
                mma16816(s[nt], ah, bh2);
                mma16816(s[nt], ah, bl2);
                mma16816(s[nt], al, bh2);
            }
        }

        // ---- Causal mask (only last two tiles can cross the diagonal) ----
        const int rg = q0 + wid * 16 + (lane >> 2);  // row of c0,c1; +8 for c2,c3
        if (kt >= 2 * qt) {
#pragma unroll
            for (int nt = 0; nt < 8; nt++) {
                int col = kk0 + nt * 8 + 2 * (lane & 3);
                if (col > rg)          s[nt][0] = -1e30f;
                if (col + 1 > rg)      s[nt][1] = -1e30f;
                if (col > rg + 8)      s[nt][2] = -1e30f;
                if (col + 1 > rg + 8)  s[nt][3] = -1e30f;
            }
        }

        // ---- Online softmax (rows rg and rg+8; quad-lane reductions) ----
        float mt0 = -1e30f, mt1 = -1e30f;
#pragma unroll
        for (int nt = 0; nt < 8; nt++) {
            mt0 = fmaxf(mt0, fmaxf(s[nt][0], s[nt][1]));
            mt1 = fmaxf(mt1, fmaxf(s[nt][2], s[nt][3]));
        }
        mt0 = fmaxf(mt0, __shfl_xor_sync(0xffffffffu, mt0, 1));
        mt0 = fmaxf(mt0, __shfl_xor_sync(0xffffffffu, mt0, 2));
        mt1 = fmaxf(mt1, __shfl_xor_sync(0xffffffffu, mt1, 1));
        mt1 = fmaxf(mt1, __shfl_xor_sync(0xffffffffu, mt1, 2));

        float mn0 = fmaxf(m0, mt0), mn1 = fmaxf(m1, mt1);
        float a0 = __expf(m0 - mn0), a1 = __expf(m1 - mn1);
        m0 = mn0; m1 = mn1;

        float rs0 = 0.0f, rs1 = 0.0f;
#pragma unroll
        for (int nt = 0; nt < 8; nt++) {
            s[nt][0] = __expf(s[nt][0] - mn0);
            s[nt][1] = __expf(s[nt][1] - mn0);
            s[nt][2] = __expf(s[nt][2] - mn1);
            s[nt][3] = __expf(s[nt][3] - mn1);
            rs0 += s[nt][0] + s[nt][1];
            rs1 += s[nt][2] + s[nt][3];
        }
        rs0 += __shfl_xor_sync(0xffffffffu, rs0, 1);
        rs0 += __shfl_xor_sync(0xffffffffu, rs0, 2);
        rs1 += __shfl_xor_sync(0xffffffffu, rs1, 1);
        rs1 += __shfl_xor_sync(0xffffffffu, rs1, 2);
        l0 = l0 * a0 + rs0;
        l1 = l1 * a1 + rs1;

#pragma unroll
        for (int dt = 0; dt < 16; dt++) {
            o[dt][0] *= a0; o[dt][1] *= a0;
            o[dt][2] *= a1; o[dt][3] *= a1;
        }

        // ---- O += P @ V (P from S regs; V via ldmatrix.trans) ----
#pragma unroll
        for (int ks2 = 0; ks2 < 4; ks2++) {
            const float* t0 = s[2 * ks2];
            const float* t1 = s[2 * ks2 + 1];
            uint32_t ph[4], pl[4];
            ph[0] = pack_bf2(t0[0], t0[1]);
            ph[1] = pack_bf2(t0[2], t0[3]);
            ph[2] = pack_bf2(t1[0], t1[1]);
            ph[3] = pack_bf2(t1[2], t1[3]);
            {
                __nv_bfloat162 h;
                *reinterpret_cast<uint32_t*>(&h) = ph[0];
                pl[0] = pack_bf2(t0[0] - __bfloat162float(h.x), t0[1] - __bfloat162float(h.y));
                *reinterpret_cast<uint32_t*>(&h) = ph[1];
                pl[1] = pack_bf2(t0[2] - __bfloat162float(h.x), t0[3] - __bfloat162float(h.y));
                *reinterpret_cast<uint32_t*>(&h) = ph[2];
                pl[2] = pack_bf2(t1[0] - __bfloat162float(h.x), t1[1] - __bfloat162float(h.y));
                *reinterpret_cast<uint32_t*>(&h) = ph[3];
                pl[3] = pack_bf2(t1[2] - __bfloat162float(h.x), t1[3] - __bfloat162float(h.y));
            }
            uint32_t vrow = (uint32_t)((ks2 * 16 + (lane & 15)) * 128);
#pragma unroll
            for (int dt = 0; dt < 16; dt++) {
                const int p = dt >> 3;
                uint32_t bofs = vrow + (uint32_t)((dt & 7) * 16);
                uint32_t vh2[2], vl2[2];
                ldsm_x2_t(vh2, sq + F_VH + p * 8192 + SWZ(bofs));
                ldsm_x2_t(vl2, sq + F_VL + p * 8192 + SWZ(bofs));
                mma16816(o[dt], ph, vh2);
                mma16816(o[dt], ph, vl2);
                mma16816(o[dt], pl, vh2);
            }
        }
    }

    // ---- Normalize + write y [B,T,C] (head-interleaved cols) ----
    const float inv0 = 1.0f / l0;
    const float inv1 = 1.0f / l1;
    const int r0 = q0 + wid * 16 + (lane >> 2);
    float* y0 = g_y + ((size_t)b * TT + r0) * CC + (size_t)h * DD;
    float* y1 = g_y + ((size_t)b * TT + r0 + 8) * CC + (size_t)h * DD;
#pragma unroll
    for (int dt = 0; dt < 16; dt++) {
        int col = dt * 8 + 2 * (lane & 3);
        *(float2*)(y0 + col) = make_float2(o[dt][0] * inv0, o[dt][1] * inv0);
        *(float2*)(y1 + col) = make_float2(o[dt][2] * inv1, o[dt][3] * inv1);
    }
}

// ---------------------------------------------------------------------------
// Launch sequence
// ---------------------------------------------------------------------------
extern "C" void kernel_launch(void* const* d_in, const int* in_sizes, int n_in,
                              void* d_out, int out_size)
{
    (void)in_sizes; (void)n_in; (void)out_size;
    const float* x      = (const float*)d_in[0];
    const float* W_attn = (const float*)d_in[1];
    const float* b_attn = (const float*)d_in[2];
    const float* W_proj = (const float*)d_in[3];
    const float* b_proj = (const float*)d_in[4];
    float* out = (float*)d_out;

    float* qkv = nullptr; float* y = nullptr;
    __nv_bfloat16 *ah = nullptr, *al = nullptr, *bh = nullptr, *bl = nullptr;
    cudaGetSymbolAddress((void**)&qkv, g_qkv);
    cudaGetSymbolAddress((void**)&y,   g_y);
    cudaGetSymbolAddress((void**)&ah,  g_ah);
    cudaGetSymbolAddress((void**)&al,  g_al);
    cudaGetSymbolAddress((void**)&bh,  g_bh);
    cudaGetSymbolAddress((void**)&bl,  g_bl);

    cudaFuncSetAttribute(flash_kernel, cudaFuncAttributeMaxDynamicSharedMemorySize,
                         FLASH_SMEM);
    cudaFuncSetAttribute(gemm_mma_kernel, cudaFuncAttributeMaxDynamicSharedMemorySize,
                         (int)G_SMEM);

    const size_t n4 = (size_t)MM * CC / 4;

    // 1) QKV projection: bf16-split mma.sync GEMM
    split_rm_kernel<<<(unsigned)((n4 + 255) / 256), 256>>>(x, ah, al, n4);
    split_tr_kernel<<<dim3(N3 / 32, CC / 32), 256>>>(W_attn, bh, bl, CC, N3);
    gemm_mma_kernel<<<dim3(N3 / 128, MM / 128), 256, G_SMEM>>>(ah, al, bh, bl,
                                                               b_attn, qkv, N3, CC);
    // 2) Causal multi-head attention (tensor-core flash)
    flash_kernel<<<dim3(TT / 128, HH, BB), 256, FLASH_SMEM>>>();

    // 3) Output projection: bf16-split mma.sync GEMM
    split_rm_kernel<<<(unsigned)((n4 + 255) / 256), 256>>>(y, ah, al, n4);
    split_tr_kernel<<<dim3(CC / 32, CC / 32), 256>>>(W_proj, bh, bl, CC, CC);
    gemm_mma_kernel<<<dim3(CC / 128, MM / 128), 256, G_SMEM>>>(ah, al, bh, bl,
                                                               b_proj, out, CC, CC);
}

// round 12
// speedup vs baseline: 2.6012x; 1.0250x over previous
#include <cuda_runtime.h>
#include <cuda_bf16.h>
#include <cstdint>
#include <math.h>

// Problem constants
#define BB 2
#define TT 2048
#define CC 2048
#define HH 16
#define DD 128
#define MM (BB * TT)    // 4096 rows
#define N3 (3 * CC)     // 6144

// Scratch (no cudaMalloc allowed)
__device__ float g_qkv[(size_t)MM * N3];                        // fp32 qkv
__device__ float g_y[(size_t)MM * CC];                          // fp32 attention out
__device__ __align__(16) __nv_bfloat16 g_ah[(size_t)MM * CC];   // A hi (x or y)
__device__ __align__(16) __nv_bfloat16 g_al[(size_t)MM * CC];   // A lo
__device__ __align__(16) __nv_bfloat16 g_bh[(size_t)N3 * CC];   // W^T hi
__device__ __align__(16) __nv_bfloat16 g_bl[(size_t)N3 * CC];   // W^T lo

// ---------------------------------------------------------------------------
// Base-target PTX helpers (NO tcgen05/TMEM — ptxas targets compute_103)
// ---------------------------------------------------------------------------
__device__ __forceinline__ uint32_t smem_u32(const void* p) {
    uint32_t a;
    asm("{ .reg .u64 t; cvta.to.shared.u64 t, %1; cvt.u32.u64 %0, t; }" : "=r"(a) : "l"(p));
    return a;
}

#define CP_ASYNC16(dst, src) asm volatile("cp.async.cg.shared.global [%0], [%1], 16;" :: "r"(dst), "l"(src))
#define CP_COMMIT()          asm volatile("cp.async.commit_group;" ::: "memory")
#define CP_WAIT0()           asm volatile("cp.async.wait_group 0;" ::: "memory")
#define CP_WAIT1()           asm volatile("cp.async.wait_group 1;" ::: "memory")

__device__ __forceinline__ void ldsm_x4(uint32_t* r, uint32_t addr) {
    asm volatile("ldmatrix.sync.aligned.m8n8.x4.shared.b16 {%0,%1,%2,%3}, [%4];"
                 : "=r"(r[0]), "=r"(r[1]), "=r"(r[2]), "=r"(r[3]) : "r"(addr));
}
__device__ __forceinline__ void ldsm_x4_t(uint32_t* r, uint32_t addr) {
    asm volatile("ldmatrix.sync.aligned.m8n8.x4.trans.shared.b16 {%0,%1,%2,%3}, [%4];"
                 : "=r"(r[0]), "=r"(r[1]), "=r"(r[2]), "=r"(r[3]) : "r"(addr));
}
__device__ __forceinline__ void mma16816(float* d, const uint32_t* a, const uint32_t* b) {
    asm volatile(
        "mma.sync.aligned.m16n8k16.row.col.f32.bf16.bf16.f32 "
        "{%0,%1,%2,%3}, {%4,%5,%6,%7}, {%8,%9}, {%0,%1,%2,%3};"
        : "+f"(d[0]), "+f"(d[1]), "+f"(d[2]), "+f"(d[3])
        : "r"(a[0]), "r"(a[1]), "r"(a[2]), "r"(a[3]), "r"(b[0]), "r"(b[1]));
}

// SW128 swizzle on byte offsets (128B rows)
#define SWZ(o) ((uint32_t)(o) ^ (((uint32_t)(o) >> 3) & 0x70u))

__device__ __forceinline__ uint32_t pack_bf2(float a, float b) {
    __nv_bfloat162 t = __floats2bfloat162_rn(a, b);
    return *reinterpret_cast<uint32_t*>(&t);
}

// Split a float4 into packed bf16 hi (uint2) and lo (uint2)
__device__ __forceinline__ void split4(float4 v, uint2& hi, uint2& lo) {
    __nv_bfloat16 h0 = __float2bfloat16_rn(v.x);
    __nv_bfloat16 h1 = __float2bfloat16_rn(v.y);
    __nv_bfloat16 h2 = __float2bfloat16_rn(v.z);
    __nv_bfloat16 h3 = __float2bfloat16_rn(v.w);
    __nv_bfloat162 a; a.x = h0; a.y = h1;
    __nv_bfloat162 b; b.x = h2; b.y = h3;
    hi.x = *reinterpret_cast<uint32_t*>(&a);
    hi.y = *reinterpret_cast<uint32_t*>(&b);
    lo.x = pack_bf2(v.x - __bfloat162float(h0), v.y - __bfloat162float(h1));
    lo.y = pack_bf2(v.z - __bfloat162float(h2), v.w - __bfloat162float(h3));
}

// ---------------------------------------------------------------------------
// Split kernels: fp32 -> bf16 hi + bf16 lo
// ---------------------------------------------------------------------------
__global__ void split_rm_kernel(const float* __restrict__ in,
                                __nv_bfloat16* __restrict__ oh,
                                __nv_bfloat16* __restrict__ ol, size_t n4)
{
    size_t i = (size_t)blockIdx.x * blockDim.x + threadIdx.x;
    if (i >= n4) return;
    float4 v = ((const float4*)in)[i];
    uint2 hi, lo;
    split4(v, hi, lo);
    ((uint2*)oh)[i] = hi;
    ((uint2*)ol)[i] = lo;
}

// W [Kd, Nd] fp32 -> out [Nd, Kd] bf16 hi/lo (transpose via smem tile)
__global__ void split_tr_kernel(const float* __restrict__ in,
                                __nv_bfloat16* __restrict__ oh,
                                __nv_bfloat16* __restrict__ ol, int Kd, int Nd)
{
    __shared__ float t[32][33];
    int n0 = blockIdx.x * 32, k0 = blockIdx.y * 32;
    int tx = threadIdx.x & 31, ty = threadIdx.x >> 5;   // 256 thr: ty 0..7
#pragma unroll
    for (int r = 0; r < 32; r += 8)
        t[ty + r][tx] = in[(size_t)(k0 + ty + r) * Nd + n0 + tx];
    __syncthreads();
#pragma unroll
    for (int r = 0; r < 32; r += 8) {
        int n = ty + r;
        float v = t[tx][n];
        __nv_bfloat16 h = __float2bfloat16_rn(v);
        __nv_bfloat16 l = __float2bfloat16_rn(v - __bfloat162float(h));
        oh[(size_t)(n0 + n) * Kd + k0 + tx] = h;
        ol[(size_t)(n0 + n) * Kd + k0 + tx] = l;
    }
}

// ---------------------------------------------------------------------------
// bf16-split GEMM via ldmatrix + mma.sync (m16n8k16)
// BM=BN=128, BK=32, 8 warps (2x4), warp tile 64x32.
// 3-stage cp.async pipeline (wait_group 1), x4-paired B-fragment loads.
// ---------------------------------------------------------------------------
#define GBK 32
#define ATILE 16384
#define STAGE (2 * ATILE)
#define G_SMEM (3 * STAGE)             // 98304

__global__ __launch_bounds__(256, 1)
void gemm_mma_kernel(const __nv_bfloat16* __restrict__ Ah,
                     const __nv_bfloat16* __restrict__ Al,
                     const __nv_bfloat16* __restrict__ Bh,
                     const __nv_bfloat16* __restrict__ Bl,
                     const float* __restrict__ bias,
                     float* __restrict__ Co, int Ndim, int Kdim)
{
    extern __shared__ char smem[];
    const uint32_t sb = smem_u32(smem);
    const int tid  = threadIdx.x;
    const int wid  = tid >> 5;
    const int lane = tid & 31;
    const int wm   = wid & 1;
    const int wn   = wid >> 1;
    const int row0 = blockIdx.y * 128;
    const int col0 = blockIdx.x * 128;

    const __nv_bfloat16* Ahp = Ah + (size_t)row0 * Kdim;
    const __nv_bfloat16* Alp = Al + (size_t)row0 * Kdim;
    const __nv_bfloat16* Bhp = Bh + (size_t)col0 * Kdim;
    const __nv_bfloat16* Blp = Bl + (size_t)col0 * Kdim;

    float acc[4][4][4];
#pragma unroll
    for (int i = 0; i < 4; i++)
#pragma unroll
        for (int j = 0; j < 4; j++)
#pragma unroll
            for (int k = 0; k < 4; k++) acc[i][j][k] = 0.0f;

    const int NCH = Kdim >> 5;

    auto load_stage = [&](int s, int k0) {
        uint32_t as = sb + s * STAGE;
        uint32_t bs = as + ATILE;
#pragma unroll
        for (int it = 0; it < 4; it++) {
            int i = tid + it * 256;
            int r = i >> 3, c = i & 7;
            uint32_t d = SWZ(r * 128 + c * 16);
            const __nv_bfloat16* sa = (c < 4)
                ? (Ahp + (size_t)r * Kdim + k0 + c * 8)
                : (Alp + (size_t)r * Kdim + k0 + (c - 4) * 8);
            CP_ASYNC16(as + d, sa);
            const __nv_bfloat16* sbp = (c < 4)
                ? (Bhp + (size_t)r * Kdim + k0 + c * 8)
                : (Blp + (size_t)r * Kdim + k0 + (c - 4) * 8);
            CP_ASYNC16(bs + d, sbp);
        }
    };

    // Prologue: two stages in flight
    load_stage(0, 0);
    CP_COMMIT();
    load_stage(1, GBK);
    CP_COMMIT();

    for (int ch = 0; ch < NCH; ch++) {
        CP_WAIT1();                     // stage ch landed (<=1 group pending)
        __syncthreads();                // all warps done with stage being overwritten
        if (ch + 2 < NCH) load_stage((ch + 2) % 3, (ch + 2) * GBK);
        CP_COMMIT();

        const uint32_t as = sb + (ch % 3) * STAGE;
        const uint32_t bs = as + ATILE;

#pragma unroll
        for (int ks = 0; ks < 2; ks++) {
            uint32_t ah[4][4], al[4][4];
            {
                const int arow = wm * 64 + (lane & 15);
                const uint32_t kb = (uint32_t)(ks * 32 + ((lane >> 4) << 4));
#pragma unroll
                for (int mt = 0; mt < 4; mt++) {
                    uint32_t base = (uint32_t)((arow + mt * 16) * 128);
                    ldsm_x4(ah[mt], as + SWZ(base + kb));
                    ldsm_x4(al[mt], as + SWZ(base + kb + 64));
                }
            }
            // B fragments: x4 loads pair two n-tiles (mats {0,1} and {2,3})
            uint32_t bh4[2][4], bl4[2][4];
            {
                const uint32_t rsel = (uint32_t)((lane & 7) + ((lane >> 4) << 3));
                const uint32_t kbB = (uint32_t)(ks * 32 + (((lane >> 3) & 1) << 4));
#pragma unroll
                for (int ntp = 0; ntp < 2; ntp++) {
                    uint32_t base = (uint32_t)((wn * 32 + ntp * 16 + rsel) * 128);
                    ldsm_x4(bh4[ntp], bs + SWZ(base + kbB));
                    ldsm_x4(bl4[ntp], bs + SWZ(base + kbB + 64));
                }
            }
#pragma unroll
            for (int mt = 0; mt < 4; mt++)
#pragma unroll
                for (int ntp = 0; ntp < 2; ntp++) {
                    mma16816(acc[mt][2 * ntp],     ah[mt], &bh4[ntp][0]);
                    mma16816(acc[mt][2 * ntp],     ah[mt], &bl4[ntp][0]);
                    mma16816(acc[mt][2 * ntp],     al[mt], &bh4[ntp][0]);
                    mma16816(acc[mt][2 * ntp + 1], ah[mt], &bh4[ntp][2]);
                    mma16816(acc[mt][2 * ntp + 1], ah[mt], &bl4[ntp][2]);
                    mma16816(acc[mt][2 * ntp + 1], al[mt], &bh4[ntp][2]);
                }
        }
    }

    const int g = lane >> 2;
    const int cg = lane & 3;
#pragma unroll
    for (int mt = 0; mt < 4; mt++) {
#pragma unroll
        for (int nt = 0; nt < 4; nt++) {
            int row = row0 + wm * 64 + mt * 16 + g;
            int col = col0 + wn * 32 + nt * 8 + cg * 2;
            float b0 = __ldg(bias + col);
            float b1 = __ldg(bias + col + 1);
            float2 o0 = make_float2(acc[mt][nt][0] + b0, acc[mt][nt][1] + b1);
            float2 o1 = make_float2(acc[mt][nt][2] + b0, acc[mt][nt][3] + b1);
            *(float2*)(Co + (size_t)row * Ndim + col)       = o0;
            *(float2*)(Co + (size_t)(row + 8) * Ndim + col) = o1;
        }
    }
}

// ---------------------------------------------------------------------------
// Tensor-core causal flash attention: g_qkv -> g_y
// BM=128 q rows/block, BN=64 keys/tile, 256 threads = 8 warps x 16-row strips.
// x4-paired K/V fragment loads; reversed qt order for tail packing.
// ---------------------------------------------------------------------------
#define F_QH 0          // 2 panels * 16384
#define F_QL 32768
#define F_KH 65536      // 2 panels * 8192
#define F_KL 81920
#define F_VH 98304      // 2 panels * 8192
#define F_VL 114688
#define FLASH_SMEM 131072

__global__ __launch_bounds__(256, 1)
void flash_kernel()
{
    extern __shared__ char fsm[];
    const uint32_t sq = smem_u32(fsm);
    const int tid  = threadIdx.x;
    const int wid  = tid >> 5;
    const int lane = tid & 31;
    const int qt = gridDim.x - 1 - blockIdx.x;   // big tiles first
    const int h  = blockIdx.y;
    const int b  = blockIdx.z;
    const float scale = 0.08838834764831845f;  // 1/sqrt(128)

    const size_t base = ((size_t)b * TT) * N3 + (size_t)h * DD;
    const float* Qg = g_qkv + base;            // row stride N3
    const float* Kg = g_qkv + base + CC;
    const float* Vg = g_qkv + base + 2 * CC;
    const int q0 = qt * 128;

    // ---- Load Q tile (128 x 128) once: scale, split, swizzled panels ----
#pragma unroll
    for (int it = 0; it < 16; it++) {
        int idx = tid + it * 256;              // 0..4095
        int r = idx >> 5, c = idx & 31;        // r=q row, c=chunk of 4 d
        float4 v = *(const float4*)(Qg + (size_t)(q0 + r) * N3 + c * 4);
        v.x *= scale; v.y *= scale; v.z *= scale; v.w *= scale;
        uint2 hi, lo;
        split4(v, hi, lo);
        int p = c >> 4;
        uint32_t off = SWZ((uint32_t)(r * 128 + (c & 15) * 8));
        *(uint2*)(fsm + F_QH + p * 16384 + off) = hi;
        *(uint2*)(fsm + F_QL + p * 16384 + off) = lo;
    }

    // ---- State ----
    float o[16][4];
#pragma unroll
    for (int i = 0; i < 16; i++)
#pragma unroll
        for (int j = 0; j < 4; j++) o[i][j] = 0.0f;
    float m0 = -1e30f, m1 = -1e30f, l0 = 0.0f, l1 = 0.0f;

    const int nkt = 2 * qt + 2;

    for (int kt = 0; kt < nkt; kt++) {
        const int kk0 = kt * 64;
        __syncthreads();
        // ---- Load K, V tiles (64 x 128) ----
#pragma unroll
        for (int it = 0; it < 8; it++) {
            int idx = tid + it * 256;          // 0..2047
            int r = idx >> 5, c = idx & 31;
            int p = c >> 4;
            uint32_t off = SWZ((uint32_t)(r * 128 + (c & 15) * 8));
            float4 kv = *(const float4*)(Kg + (size_t)(kk0 + r) * N3 + c * 4);
            uint2 hi, lo;
            split4(kv, hi, lo);
            *(uint2*)(fsm + F_KH + p * 8192 + off) = hi;
            *(uint2*)(fsm + F_KL + p * 8192 + off) = lo;
            float4 vv = *(const float4*)(Vg + (size_t)(kk0 + r) * N3 + c * 4);
            split4(vv, hi, lo);
            *(uint2*)(fsm + F_VH + p * 8192 + off) = hi;
            *(uint2*)(fsm + F_VL + p * 8192 + off) = lo;
        }
        __syncthreads();

        // ---- S = Q @ K^T (3-pass split; x4-paired K frags) ----
        float s[8][4];
#pragma unroll
        for (int nt = 0; nt < 8; nt++)
#pragma unroll
            for (int j = 0; j < 4; j++) s[nt][j] = 0.0f;

#pragma unroll
        for (int ks = 0; ks < 8; ks++) {
            const int p = ks >> 2;
            uint32_t ah[4], al[4];
            {
                uint32_t kb = (uint32_t)((ks & 3) * 32 + ((lane >> 4) << 4));
                uint32_t aofs = (uint32_t)((wid * 16 + (lane & 15)) * 128) + kb;
                ldsm_x4(ah, sq + F_QH + p * 16384 + SWZ(aofs));
                ldsm_x4(al, sq + F_QL + p * 16384 + SWZ(aofs));
            }
            const uint32_t kb2 = (uint32_t)((ks & 3) * 32 + (((lane >> 3) & 1) << 4));
            const uint32_t rsel = (uint32_t)((lane & 7) + ((lane >> 4) << 3));
#pragma unroll
            for (int ntp = 0; ntp < 4; ntp++) {
                uint32_t bofs = (uint32_t)((ntp * 16 + rsel) * 128) + kb2;
                uint32_t bh4[4], bl4[4];
                ldsm_x4(bh4, sq + F_KH + p * 8192 + SWZ(bofs));
                ldsm_x4(bl4, sq + F_KL + p * 8192 + SWZ(bofs));
                mma16816(s[2 * ntp],     ah, &bh4[0]);
                mma16816(s[2 * ntp],     ah, &bl4[0]);
                mma16816(s[2 * ntp],     al, &bh4[0]);
                mma16816(s[2 * ntp + 1], ah, &bh4[2]);
                mma16816(s[2 * ntp + 1], ah, &bl4[2]);
                mma16816(s[2 * ntp + 1], al, &bh4[2]);
            }
        }

        // ---- Causal mask (only last two tiles can cross the diagonal) ----
        const int rg = q0 + wid * 16 + (lane >> 2);  // row of c0,c1; +8 for c2,c3
        if (kt >= 2 * qt) {
#pragma unroll
            for (int nt = 0; nt < 8; nt++) {
                int col = kk0 + nt * 8 + 2 * (lane & 3);
                if (col > rg)          s[nt][0] = -1e30f;
                if (col + 1 > rg)      s[nt][1] = -1e30f;
                if (col > rg + 8)      s[nt][2] = -1e30f;
                if (col + 1 > rg + 8)  s[nt][3] = -1e30f;
            }
        }

        // ---- Online softmax (rows rg and rg+8; quad-lane reductions) ----
        float mt0 = -1e30f, mt1 = -1e30f;
#pragma unroll
        for (int nt = 0; nt < 8; nt++) {
            mt0 = fmaxf(mt0, fmaxf(s[nt][0], s[nt][1]));
            mt1 = fmaxf(mt1, fmaxf(s[nt][2], s[nt][3]));
        }
        mt0 = fmaxf(mt0, __shfl_xor_sync(0xffffffffu, mt0, 1));
        mt0 = fmaxf(mt0, __shfl_xor_sync(0xffffffffu, mt0, 2));
        mt1 = fmaxf(mt1, __shfl_xor_sync(0xffffffffu, mt1, 1));
        mt1 = fmaxf(mt1, __shfl_xor_sync(0xffffffffu, mt1, 2));

        float mn0 = fmaxf(m0, mt0), mn1 = fmaxf(m1, mt1);
        float a0 = __expf(m0 - mn0), a1 = __expf(m1 - mn1);
        m0 = mn0; m1 = mn1;

        float rs0 = 0.0f, rs1 = 0.0f;
#pragma unroll
        for (int nt = 0; nt < 8; nt++) {
            s[nt][0] = __expf(s[nt][0] - mn0);
            s[nt][1] = __expf(s[nt][1] - mn0);
            s[nt][2] = __expf(s[nt][2] - mn1);
            s[nt][3] = __expf(s[nt][3] - mn1);
            rs0 += s[nt][0] + s[nt][1];
            rs1 += s[nt][2] + s[nt][3];
        }
        rs0 += __shfl_xor_sync(0xffffffffu, rs0, 1);
        rs0 += __shfl_xor_sync(0xffffffffu, rs0, 2);
        rs1 += __shfl_xor_sync(0xffffffffu, rs1, 1);
        rs1 += __shfl_xor_sync(0xffffffffu, rs1, 2);
        l0 = l0 * a0 + rs0;
        l1 = l1 * a1 + rs1;

#pragma unroll
        for (int dt = 0; dt < 16; dt++) {
            o[dt][0] *= a0; o[dt][1] *= a0;
            o[dt][2] *= a1; o[dt][3] *= a1;
        }

        // ---- O += P @ V (P from S regs; x4.trans-paired V frags) ----
#pragma unroll
        for (int ks2 = 0; ks2 < 4; ks2++) {
            const float* t0 = s[2 * ks2];
            const float* t1 = s[2 * ks2 + 1];
            uint32_t ph[4], pl[4];
            ph[0] = pack_bf2(t0[0], t0[1]);
            ph[1] = pack_bf2(t0[2], t0[3]);
            ph[2] = pack_bf2(t1[0], t1[1]);
            ph[3] = pack_bf2(t1[2], t1[3]);
            {
                __nv_bfloat162 hh;
                *reinterpret_cast<uint32_t*>(&hh) = ph[0];
                pl[0] = pack_bf2(t0[0] - __bfloat162float(hh.x), t0[1] - __bfloat162float(hh.y));
                *reinterpret_cast<uint32_t*>(&hh) = ph[1];
                pl[1] = pack_bf2(t0[2] - __bfloat162float(hh.x), t0[3] - __bfloat162float(hh.y));
                *reinterpret_cast<uint32_t*>(&hh) = ph[2];
                pl[2] = pack_bf2(t1[0] - __bfloat162float(hh.x), t1[1] - __bfloat162float(hh.y));
                *reinterpret_cast<uint32_t*>(&hh) = ph[3];
                pl[3] = pack_bf2(t1[2] - __bfloat162float(hh.x), t1[3] - __bfloat162float(hh.y));
            }
            uint32_t vrow = (uint32_t)((ks2 * 16 + (lane & 15)) * 128);
#pragma unroll
            for (int dtp = 0; dtp < 8; dtp++) {
                const int p = dtp >> 2;        // dt = 2*dtp -> panel (2*dtp)>>3
                uint32_t colsel = (uint32_t)(((2 * dtp) & 7) + (lane >> 4));
                uint32_t bofs = vrow + colsel * 16;
                uint32_t vh4[4], vl4[4];
                ldsm_x4_t(vh4, sq + F_VH + p * 8192 + SWZ(bofs));
                ldsm_x4_t(vl4, sq + F_VL + p * 8192 + SWZ(bofs));
                mma16816(o[2 * dtp],     ph, &vh4[0]);
                mma16816(o[2 * dtp],     ph, &vl4[0]);
                mma16816(o[2 * dtp],     pl, &vh4[0]);
                mma16816(o[2 * dtp + 1], ph, &vh4[2]);
                mma16816(o[2 * dtp + 1], ph, &vl4[2]);
                mma16816(o[2 * dtp + 1], pl, &vh4[2]);
            }
        }
    }

    // ---- Normalize + write y [B,T,C] (head-interleaved cols) ----
    const float inv0 = 1.0f / l0;
    const float inv1 = 1.0f / l1;
    const int r0 = q0 + wid * 16 + (lane >> 2);
    float* y0 = g_y + ((size_t)b * TT + r0) * CC + (size_t)h * DD;
    float* y1 = g_y + ((size_t)b * TT + r0 + 8) * CC + (size_t)h * DD;
#pragma unroll
    for (int dt = 0; dt < 16; dt++) {
        int col = dt * 8 + 2 * (lane & 3);
        *(float2*)(y0 + col) = make_float2(o[dt][0] * inv0, o[dt][1] * inv0);
        *(float2*)(y1 + col) = make_float2(o[dt][2] * inv1, o[dt][3] * inv1);
    }
}

// ---------------------------------------------------------------------------
// Launch sequence
// ---------------------------------------------------------------------------
extern "C" void kernel_launch(void* const* d_in, const int* in_sizes, int n_in,
                              void* d_out, int out_size)
{
    (void)in_sizes; (void)n_in; (void)out_size;
    const float* x      = (const float*)d_in[0];
    const float* W_attn = (const float*)d_in[1];
    const float* b_attn = (const float*)d_in[2];
    const float* W_proj = (const float*)d_in[3];
    const float* b_proj = (const float*)d_in[4];
    float* out = (float*)d_out;

    float* qkv = nullptr; float* y = nullptr;
    __nv_bfloat16 *ah = nullptr, *al = nullptr, *bh = nullptr, *bl = nullptr;
    cudaGetSymbolAddress((void**)&qkv, g_qkv);
    cudaGetSymbolAddress((void**)&y,   g_y);
    cudaGetSymbolAddress((void**)&ah,  g_ah);
    cudaGetSymbolAddress((void**)&al,  g_al);
    cudaGetSymbolAddress((void**)&bh,  g_bh);
    cudaGetSymbolAddress((void**)&bl,  g_bl);

    cudaFuncSetAttribute(flash_kernel, cudaFuncAttributeMaxDynamicSharedMemorySize,
                         FLASH_SMEM);
    cudaFuncSetAttribute(gemm_mma_kernel, cudaFuncAttributeMaxDynamicSharedMemorySize,
                         (int)G_SMEM);

    const size_t n4 = (size_t)MM * CC / 4;

    // 1) QKV projection: bf16-split mma.sync GEMM
    split_rm_kernel<<<(unsigned)((n4 + 255) / 256), 256>>>(x, ah, al, n4);
    split_tr_kernel<<<dim3(N3 / 32, CC / 32), 256>>>(W_attn, bh, bl, CC, N3);
    gemm_mma_kernel<<<dim3(N3 / 128, MM / 128), 256, G_SMEM>>>(ah, al, bh, bl,
                                                               b_attn, qkv, N3, CC);
    // 2) Causal multi-head attention (tensor-core flash)
    flash_kernel<<<dim3(TT / 128, HH, BB), 256, FLASH_SMEM>>>();

    // 3) Output projection: bf16-split mma.sync GEMM
    split_rm_kernel<<<(unsigned)((n4 + 255) / 256), 256>>>(y, ah, al, n4);
    split_tr_kernel<<<dim3(CC / 32, CC / 32), 256>>>(W_proj, bh, bl, CC, CC);
    gemm_mma_kernel<<<dim3(CC / 128, MM / 128), 256, G_SMEM>>>(ah, al, bh, bl,
                                                               b_proj, out, CC, CC);
}